// round 12
// baseline (speedup 1.0000x reference)
#include <cuda_runtime.h>
#include <cuda_fp16.h>

#define NN 4096
#define ITERS 21            // 20 scan iterations + 1 last-iterate
#define GB 256              // blocks; 2 per SM (148 SMs -> all wave-1 co-resident)
#define TB 512              // threads per block (16 warps)
#define RPB (NN / GB)       // 16 rows per block  (phase A ownership)
#define CPB (NN / GB)       // 16 cols per block  (phase B ownership)

// ---- device-global scratch (static allocation; no cudaMalloc allowed) ----
__device__ __align__(16) __half d_Kh[(size_t)NN * NN];  // K = param^2 in fp16 (32 MB, L2-resident)
__device__ float d_AF[NN];
__device__ float d_BF[NN];
__device__ unsigned int d_bar;   // barrier counter; reset to 0 after each solve by reset_kernel

// ---------------------------------------------------------------------------
// Grid barrier, low-contention version.
//  - Arrival: atomicAdd with UNUSED return -> ptxas emits RED.E.ADD (no
//    round-trip, ~1 cyc/op at the LTS even for a single address).
//  - Wait: poll against a STATIC target (barrier_index+1)*GB, valid because
//    d_bar starts at 0 every launch (reset_kernel runs after solve, stream-
//    ordered inside the captured graph).
//  - __threadfence() is gpu-scope -> CCTL.IVALL: post-barrier reads of
//    d_AF/d_BF see other SMs' writes (L1 invalidated before the block's
//    threads are released by the trailing __syncthreads).
// ---------------------------------------------------------------------------
__device__ __forceinline__ void grid_sync(unsigned int target) {
    __syncthreads();
    if (threadIdx.x == 0) {
        __threadfence();                                   // release
        atomicAdd(&d_bar, 1u);                             // return unused -> RED
        while (*((volatile unsigned int*)&d_bar) < target) { }
        __threadfence();                                   // acquire (L1 invalidate)
    }
    __syncthreads();
}

__global__ void reset_kernel() { d_bar = 0u; }

// ---------------------------------------------------------------------------
// Setup: Kh = float2half(param^2). 8 elements/thread, exact coverage.
// ---------------------------------------------------------------------------
__global__ void setup_kernel(const float* __restrict__ param) {
    size_t base = ((size_t)blockIdx.x * blockDim.x + threadIdx.x) * 8;
    float4 p0 = *(const float4*)(param + base);
    float4 p1 = *(const float4*)(param + base + 4);
    __half2 hs[4];
    hs[0] = __floats2half2_rn(p0.x * p0.x, p0.y * p0.y);
    hs[1] = __floats2half2_rn(p0.z * p0.z, p0.w * p0.w);
    hs[2] = __floats2half2_rn(p1.x * p1.x, p1.y * p1.y);
    hs[3] = __floats2half2_rn(p1.z * p1.z, p1.w * p1.w);
    *reinterpret_cast<uint4*>(d_Kh + base) = *reinterpret_cast<uint4*>(hs);
}

// ---------------------------------------------------------------------------
// Persistent solver: 256 blocks x 16 warps, 2 blocks/SM.
//  Phase A (16 rows/block, 1 row/warp): 4 fp32 accumulators; K + BF loads
//    batched 2 segments deep (6 LDG.128 in flight per warp, x32 warps/SM).
//  Phase B (16 cols/block): lane -> (rsub = lane>>2, colgroup g = lane&3);
//    warp w covers rows {8w + rsub + 128*step}; per step one uint2 (8 B),
//    warp reads 8 rows x 32 B = whole sectors, block-exclusive.
//  Phase C: C = param^2 * AF[:,None] * BF[None,:] with exact fp32 param.
// ---------------------------------------------------------------------------
__global__ void __launch_bounds__(TB, 2) solve_kernel(
    const float* __restrict__ AT,
    const float* __restrict__ BT,
    const float* __restrict__ param,
    float* __restrict__ C)
{
    __shared__ float sAF[NN];         // phase B: AF for broadcast reads
    __shared__ float sPart[16 * 16];  // phase B cross-warp partials

    const int tid  = threadIdx.x;
    const int lane = tid & 31;
    const int w    = tid >> 5;        // warp 0..15
    const int b    = blockIdx.x;
    const int r0   = b * RPB;
    const int c0   = b * CPB;

    unsigned int bar_gen = 0;

    for (int it = 0; it < ITERS; ++it) {
        // ---------------- Phase A: row dots (1 row per warp) ----------------
        const float4* __restrict__ bf4 =
            (const float4*)((it == 0) ? BT : (const float*)d_BF);   // BF_0 = BT

        const int row = r0 + w;
        const uint4* __restrict__ kr = (const uint4*)(d_Kh + (size_t)row * NN);

        float acc[4] = {0.f, 0.f, 0.f, 0.f};

        #pragma unroll
        for (int c = 0; c < 8; ++c) {          // 8 chunks x 2 segs = 16 segs/lane
            uint4  kv[2];
            float4 bb[2][2];
            #pragma unroll
            for (int s = 0; s < 2; ++s) {      // batch loads: 2 K + 4 BF LDG.128 in flight
                int g = lane + 32 * (c * 2 + s);
                kv[s]    = kr[g];
                bb[s][0] = bf4[2 * g];
                bb[s][1] = bf4[2 * g + 1];
            }
            #pragma unroll
            for (int s = 0; s < 2; ++s) {
                float2 x;
                x = __half22float2(*(const __half2*)&kv[s].x);
                acc[0] = fmaf(x.x, bb[s][0].x, acc[0]); acc[1] = fmaf(x.y, bb[s][0].y, acc[1]);
                x = __half22float2(*(const __half2*)&kv[s].y);
                acc[2] = fmaf(x.x, bb[s][0].z, acc[2]); acc[3] = fmaf(x.y, bb[s][0].w, acc[3]);
                x = __half22float2(*(const __half2*)&kv[s].z);
                acc[0] = fmaf(x.x, bb[s][1].x, acc[0]); acc[1] = fmaf(x.y, bb[s][1].y, acc[1]);
                x = __half22float2(*(const __half2*)&kv[s].w);
                acc[2] = fmaf(x.x, bb[s][1].z, acc[2]); acc[3] = fmaf(x.y, bb[s][1].w, acc[3]);
            }
        }
        float a = (acc[0] + acc[1]) + (acc[2] + acc[3]);
        #pragma unroll
        for (int off = 16; off > 0; off >>= 1)
            a += __shfl_xor_sync(0xffffffffu, a, off);
        if (lane == 0)
            d_AF[row] = AT[row] / (1.0f + a);

        bar_gen += GB;
        grid_sync(bar_gen);

        // ---------------- Phase B: column-slab sums ----------------
        for (int i = tid; i < NN; i += TB) sAF[i] = d_AF[i];
        __syncthreads();

        const int rsub = lane >> 2;            // 0..7
        const int g    = lane & 3;             // cols c0 + 4g .. 4g+3
        const __half* kb = d_Kh + (size_t)(w * 8 + rsub) * NN + c0 + g * 4;
        float p0 = 0.f, p1 = 0.f, p2 = 0.f, p3 = 0.f;
        #pragma unroll 8
        for (int step = 0; step < NN / 128; ++step) {        // 32 steps
            int   rowi = w * 8 + rsub + step * 128;
            uint2 kv   = *(const uint2*)(kb + (size_t)step * 128 * NN);
            float af   = sAF[rowi];                          // broadcast, conflict-free
            float2 x = __half22float2(*(const __half2*)&kv.x);
            float2 y = __half22float2(*(const __half2*)&kv.y);
            p0 = fmaf(af, x.x, p0); p1 = fmaf(af, x.y, p1);
            p2 = fmaf(af, y.x, p2); p3 = fmaf(af, y.y, p3);
        }
        #pragma unroll
        for (int off = 4; off <= 16; off <<= 1) {            // fold rsub groups
            p0 += __shfl_xor_sync(0xffffffffu, p0, off);
            p1 += __shfl_xor_sync(0xffffffffu, p1, off);
            p2 += __shfl_xor_sync(0xffffffffu, p2, off);
            p3 += __shfl_xor_sync(0xffffffffu, p3, off);
        }
        if (rsub == 0) {
            sPart[w * 16 + g * 4 + 0] = p0;
            sPart[w * 16 + g * 4 + 1] = p1;
            sPart[w * 16 + g * 4 + 2] = p2;
            sPart[w * 16 + g * 4 + 3] = p3;
        }
        __syncthreads();
        if (tid < CPB) {                                     // deterministic cross-warp reduce
            float s = 0.f;
            #pragma unroll
            for (int ww = 0; ww < 16; ++ww) s += sPart[ww * 16 + tid];
            d_BF[c0 + tid] = BT[c0 + tid] / (1.0f + s);
        }

        bar_gen += GB;
        grid_sync(bar_gen);
    }

    // ---------------- Phase C: C[r][j] = param^2 * AF[r] * BF[j] (exact fp32 K) ----------------
    const float4* __restrict__ bfv = (const float4*)d_BF;    // L1 fresh after last grid_sync
    {
        const int   row = r0 + w;                            // 1 row per warp
        const float af  = d_AF[row];
        const float4* prow = (const float4*)(param + (size_t)row * NN);
        float4*       crow = (float4*)(C + (size_t)row * NN);
        #pragma unroll 4
        for (int seg = 0; seg < 32; ++seg) {
            int idx = lane + 32 * seg;
            float4 p = prow[idx];
            float4 f = bfv[idx];
            float4 o;
            o.x = p.x * p.x * af * f.x;
            o.y = p.y * p.y * af * f.y;
            o.z = p.z * p.z * af * f.z;
            o.w = p.w * p.w * af * f.w;
            crow[idx] = o;
        }
    }
}

// ---------------------------------------------------------------------------
extern "C" void kernel_launch(void* const* d_in, const int* in_sizes, int n_in,
                              void* d_out, int out_size) {
    // param is the 16M-element input; AT, BT are the two 4096-element inputs in order.
    int pi = 2;
    for (int i = 0; i < n_in; ++i)
        if (in_sizes[i] == NN * NN) pi = i;
    const float* vecs[2] = {nullptr, nullptr};
    int k = 0;
    for (int i = 0; i < n_in && k < 2; ++i)
        if (i != pi) vecs[k++] = (const float*)d_in[i];
    const float* AT    = vecs[0];
    const float* BT    = vecs[1];
    const float* param = (const float*)d_in[pi];
    float* C = (float*)d_out;

    // Kh = fp16(param^2): 16,777,216 / (256*8) = 8192 blocks exact.
    setup_kernel<<<8192, 256>>>(param);
    // Persistent solver: 256 blocks, 2/SM -> all co-resident (barrier-safe).
    solve_kernel<<<GB, TB>>>(AT, BT, param, C);
    // Restore d_bar = 0 for the next replay (stream-ordered; graph-capturable).
    reset_kernel<<<1, 1>>>();
}

// round 13
// speedup vs baseline: 1.1265x; 1.1265x over previous
#include <cuda_runtime.h>
#include <cuda_fp16.h>

#define NN 4096
#define ITERS 21              // 20 scan iterations + 1 last-iterate
#define GB 128                // blocks, 1/SM, all wave-1 co-resident (barrier-safe)
#define TB 512                // threads (16 warps)
#define ROWS_S 28             // rows held in smem per block   (128*28 = 3584)
#define ROWS_L 4              // rows left in L2 per block     (128*4  =  512)
#define ROW0_L (GB * ROWS_S)  // first L2-resident row (3584)
#define CPB 32                // columns owned per block (phase B reduce)
#define SLAB_BYTES (ROWS_S * NN * 2)   // 229376 B dynamic smem

// ---- device-global scratch (static; no cudaMalloc allowed) ----
__device__ __align__(16) __half d_Kh[(size_t)NN * NN];  // K=param^2 fp16 (32MB, L2)
__device__ __align__(16) float  d_Part[(size_t)GB * NN]; // phase-B partials (2MB)
__device__ float d_AF[NN];
__device__ float d_BF[NN];
__device__ unsigned int d_bar;  // reset to 0 after each solve by reset_kernel

// ---------------------------------------------------------------------------
// Grid barrier: returnless atomicAdd arrival (RED, ~1cyc/op), static target.
// __threadfence() = gpu scope -> CCTL.IVALL, so post-barrier LDGs see fresh
// d_BF/d_AF/d_Part despite L1 caching.
// ---------------------------------------------------------------------------
__device__ __forceinline__ void grid_sync(unsigned int target) {
    __syncthreads();
    if (threadIdx.x == 0) {
        __threadfence();                          // release
        atomicAdd(&d_bar, 1u);                    // return unused -> RED
        while (*((volatile unsigned int*)&d_bar) < target) { }
        __threadfence();                          // acquire (L1 invalidate)
    }
    __syncthreads();
}

__global__ void reset_kernel() { d_bar = 0u; }

// ---------------------------------------------------------------------------
// Setup: Kh = float2half(param^2). 8 elems/thread, exact coverage.
// ---------------------------------------------------------------------------
__global__ void setup_kernel(const float* __restrict__ param) {
    size_t base = ((size_t)blockIdx.x * blockDim.x + threadIdx.x) * 8;
    float4 p0 = *(const float4*)(param + base);
    float4 p1 = *(const float4*)(param + base + 4);
    __half2 hs[4];
    hs[0] = __floats2half2_rn(p0.x * p0.x, p0.y * p0.y);
    hs[1] = __floats2half2_rn(p0.z * p0.z, p0.w * p0.w);
    hs[2] = __floats2half2_rn(p1.x * p1.x, p1.y * p1.y);
    hs[3] = __floats2half2_rn(p1.z * p1.z, p1.w * p1.w);
    *reinterpret_cast<uint4*>(d_Kh + base) = *reinterpret_cast<uint4*>(hs);
}

// ---------------------------------------------------------------------------
// Persistent solver, smem-resident K slab.
//  Block b owns: smem rows [28b,28b+28), L2 rows [3584+4b,+4), cols [32b,+32).
//  Iteration:
//    A:  AF[own rows] = AT/(1 + K_row . BF)          (slab LDS + 4 L2 rows)
//    Bp: Part[b][c]   = sum_{own rows} AF[i]K[i][c]  (slab LDS, no barrier vs A)
//    -- grid_sync --
//    Br: BF[own cols] = BT/(1 + sum_b' Part[b'][c])
//    -- grid_sync --
//  Phase C: C = param^2 * AF x BF  (exact fp32 param).
// ---------------------------------------------------------------------------
__global__ void __launch_bounds__(TB, 1) solve_kernel(
    const float* __restrict__ AT,
    const float* __restrict__ BT,
    const float* __restrict__ param,
    float* __restrict__ C)
{
    extern __shared__ __align__(16) char smem_raw[];
    __half* slab = (__half*)smem_raw;            // [ROWS_S][NN]
    __shared__ float sAFs[ROWS_S + ROWS_L];      // this block's AF values

    const int tid  = threadIdx.x;
    const int lane = tid & 31;
    const int w    = tid >> 5;                   // warp 0..15
    const int b    = blockIdx.x;
    const int c0   = b * CPB;

    // ---- load this block's 28-row slab from d_Kh (L2-resident) ----
    {
        const uint4* src = (const uint4*)(d_Kh + (size_t)b * ROWS_S * NN);
        uint4*       dst = (uint4*)slab;
        #pragma unroll
        for (int i = 0; i < (ROWS_S * NN / 8) / TB; ++i)   // 28 uint4 per thread
            dst[tid + i * TB] = src[tid + i * TB];
    }
    __syncthreads();

    unsigned int bar_gen = 0;

    for (int it = 0; it < ITERS; ++it) {
        // ================= Phase A: row dots =================
        const float4* __restrict__ bf4 =
            (const float4*)((it == 0) ? BT : (const float*)d_BF);   // BF_0 = BT

        if (w < 14) {
            // two smem rows per warp: local rows 2w, 2w+1
            #pragma unroll
            for (int rr = 0; rr < 2; ++rr) {
                const int rl = w * 2 + rr;
                const uint4* kr = (const uint4*)(slab + (size_t)rl * NN);
                float acc[4] = {0.f, 0.f, 0.f, 0.f};
                #pragma unroll
                for (int cch = 0; cch < 16; ++cch) {
                    int g = lane + 32 * cch;
                    uint4  kv = kr[g];                 // LDS.128: 8 halves
                    float4 b0 = bf4[2 * g];
                    float4 b1 = bf4[2 * g + 1];
                    float2 x;
                    x = __half22float2(*(const __half2*)&kv.x);
                    acc[0] = fmaf(x.x, b0.x, acc[0]); acc[1] = fmaf(x.y, b0.y, acc[1]);
                    x = __half22float2(*(const __half2*)&kv.y);
                    acc[2] = fmaf(x.x, b0.z, acc[2]); acc[3] = fmaf(x.y, b0.w, acc[3]);
                    x = __half22float2(*(const __half2*)&kv.z);
                    acc[0] = fmaf(x.x, b1.x, acc[0]); acc[1] = fmaf(x.y, b1.y, acc[1]);
                    x = __half22float2(*(const __half2*)&kv.w);
                    acc[2] = fmaf(x.x, b1.z, acc[2]); acc[3] = fmaf(x.y, b1.w, acc[3]);
                }
                float a = (acc[0] + acc[1]) + (acc[2] + acc[3]);
                #pragma unroll
                for (int off = 16; off > 0; off >>= 1)
                    a += __shfl_xor_sync(0xffffffffu, a, off);
                if (lane == 0) {
                    const int row = b * ROWS_S + rl;
                    float af = AT[row] / (1.0f + a);
                    sAFs[rl]  = af;
                    d_AF[row] = af;
                }
            }
        } else {
            // warps 14,15: two L2 rows each (local 0..3)
            #pragma unroll
            for (int rr = 0; rr < 2; ++rr) {
                const int ll  = (w - 14) * 2 + rr;           // 0..3
                const int row = ROW0_L + b * ROWS_L + ll;
                const uint4* kr = (const uint4*)(d_Kh + (size_t)row * NN);
                float acc[4] = {0.f, 0.f, 0.f, 0.f};
                #pragma unroll
                for (int cch = 0; cch < 16; ++cch) {
                    int g = lane + 32 * cch;
                    uint4  kv = kr[g];                 // LDG.128 (L2 hit)
                    float4 b0 = bf4[2 * g];
                    float4 b1 = bf4[2 * g + 1];
                    float2 x;
                    x = __half22float2(*(const __half2*)&kv.x);
                    acc[0] = fmaf(x.x, b0.x, acc[0]); acc[1] = fmaf(x.y, b0.y, acc[1]);
                    x = __half22float2(*(const __half2*)&kv.y);
                    acc[2] = fmaf(x.x, b0.z, acc[2]); acc[3] = fmaf(x.y, b0.w, acc[3]);
                    x = __half22float2(*(const __half2*)&kv.z);
                    acc[0] = fmaf(x.x, b1.x, acc[0]); acc[1] = fmaf(x.y, b1.y, acc[1]);
                    x = __half22float2(*(const __half2*)&kv.w);
                    acc[2] = fmaf(x.x, b1.z, acc[2]); acc[3] = fmaf(x.y, b1.w, acc[3]);
                }
                float a = (acc[0] + acc[1]) + (acc[2] + acc[3]);
                #pragma unroll
                for (int off = 16; off > 0; off >>= 1)
                    a += __shfl_xor_sync(0xffffffffu, a, off);
                if (lane == 0) {
                    float af = AT[row] / (1.0f + a);
                    sAFs[ROWS_S + ll] = af;
                    d_AF[row] = af;
                }
            }
        }
        __syncthreads();   // sAFs ready (block-local; no grid barrier needed)

        // ====== Phase B-partial: Part[b][c] = sum_{own rows} AF[i]*K[i][c] ======
        // thread t owns 8 consecutive columns [8t, 8t+8)
        {
            float acc[8] = {0.f,0.f,0.f,0.f,0.f,0.f,0.f,0.f};
            const uint4* slab4 = (const uint4*)slab;      // 512 uint4 per row
            #pragma unroll 4
            for (int r = 0; r < ROWS_S; ++r) {
                uint4 kv = slab4[r * (NN / 8) + tid];     // conflict-free LDS.128
                float af = sAFs[r];                        // broadcast
                float2 x;
                x = __half22float2(*(const __half2*)&kv.x);
                acc[0] = fmaf(af, x.x, acc[0]); acc[1] = fmaf(af, x.y, acc[1]);
                x = __half22float2(*(const __half2*)&kv.y);
                acc[2] = fmaf(af, x.x, acc[2]); acc[3] = fmaf(af, x.y, acc[3]);
                x = __half22float2(*(const __half2*)&kv.z);
                acc[4] = fmaf(af, x.x, acc[4]); acc[5] = fmaf(af, x.y, acc[5]);
                x = __half22float2(*(const __half2*)&kv.w);
                acc[6] = fmaf(af, x.x, acc[6]); acc[7] = fmaf(af, x.y, acc[7]);
            }
            #pragma unroll
            for (int r = 0; r < ROWS_L; ++r) {
                const int row = ROW0_L + b * ROWS_L + r;
                uint4 kv = ((const uint4*)(d_Kh + (size_t)row * NN))[tid];
                float af = sAFs[ROWS_S + r];
                float2 x;
                x = __half22float2(*(const __half2*)&kv.x);
                acc[0] = fmaf(af, x.x, acc[0]); acc[1] = fmaf(af, x.y, acc[1]);
                x = __half22float2(*(const __half2*)&kv.y);
                acc[2] = fmaf(af, x.x, acc[2]); acc[3] = fmaf(af, x.y, acc[3]);
                x = __half22float2(*(const __half2*)&kv.z);
                acc[4] = fmaf(af, x.x, acc[4]); acc[5] = fmaf(af, x.y, acc[5]);
                x = __half22float2(*(const __half2*)&kv.w);
                acc[6] = fmaf(af, x.x, acc[6]); acc[7] = fmaf(af, x.y, acc[7]);
            }
            float4* outp = (float4*)(d_Part + (size_t)b * NN + tid * 8);
            outp[0] = make_float4(acc[0], acc[1], acc[2], acc[3]);
            outp[1] = make_float4(acc[4], acc[5], acc[6], acc[7]);
        }

        bar_gen += GB;
        grid_sync(bar_gen);

        // ====== Phase B-reduce: BF[own cols] over 128 partials ======
        {
            const int col   = c0 + (tid >> 4);        // 32 cols x 16 threads
            const int chunk = tid & 15;               // partial-blocks chunk*8..+8
            float s = 0.f;
            #pragma unroll
            for (int j = 0; j < 8; ++j)
                s += d_Part[(size_t)(chunk * 8 + j) * NN + col];
            #pragma unroll
            for (int off = 8; off > 0; off >>= 1)
                s += __shfl_down_sync(0xffffffffu, s, off, 16);
            if (chunk == 0)
                d_BF[col] = BT[col] / (1.0f + s);
        }

        bar_gen += GB;
        grid_sync(bar_gen);
    }

    // ---------------- Phase C: C = param^2 * AF x BF (exact fp32) ----------------
    const float4* __restrict__ bfv = (const float4*)d_BF;   // fresh (post-barrier)
    #pragma unroll
    for (int rr = 0; rr < 2; ++rr) {
        const int   row = b * 32 + w * 2 + rr;               // block covers 32 rows
        const float af  = d_AF[row];
        const float4* prow = (const float4*)(param + (size_t)row * NN);
        float4*       crow = (float4*)(C + (size_t)row * NN);
        #pragma unroll 4
        for (int seg = 0; seg < 32; ++seg) {
            int idx = lane + 32 * seg;
            float4 p = prow[idx];
            float4 f = bfv[idx];
            float4 o;
            o.x = p.x * p.x * af * f.x;
            o.y = p.y * p.y * af * f.y;
            o.z = p.z * p.z * af * f.z;
            o.w = p.w * p.w * af * f.w;
            crow[idx] = o;
        }
    }
}

// ---------------------------------------------------------------------------
extern "C" void kernel_launch(void* const* d_in, const int* in_sizes, int n_in,
                              void* d_out, int out_size) {
    // param is the 16M-element input; AT, BT are the two 4096-element inputs in order.
    int pi = 2;
    for (int i = 0; i < n_in; ++i)
        if (in_sizes[i] == NN * NN) pi = i;
    const float* vecs[2] = {nullptr, nullptr};
    int k = 0;
    for (int i = 0; i < n_in && k < 2; ++i)
        if (i != pi) vecs[k++] = (const float*)d_in[i];
    const float* AT    = vecs[0];
    const float* BT    = vecs[1];
    const float* param = (const float*)d_in[pi];
    float* C = (float*)d_out;

    // Opt into 224 KB dynamic smem (idempotent; host-side attr, not captured).
    static bool attr_done = false;
    if (!attr_done) {
        cudaFuncSetAttribute(solve_kernel,
                             cudaFuncAttributeMaxDynamicSharedMemorySize, SLAB_BYTES);
        attr_done = true;
    }

    // Kh = fp16(param^2): 16,777,216 / (256*8) = 8192 blocks exact.
    setup_kernel<<<8192, 256>>>(param);
    // Persistent solver: 128 blocks, 1/SM, co-resident (barrier-safe).
    solve_kernel<<<GB, TB, SLAB_BYTES>>>(AT, BT, param, C);
    // Restore d_bar = 0 for the next replay (stream-ordered; graph-capturable).
    reset_kernel<<<1, 1>>>();
}

// round 15
// speedup vs baseline: 1.3649x; 1.2116x over previous
#include <cuda_runtime.h>
#include <cuda_fp16.h>

#define NN 4096
#define ITERS 21              // 20 scan iterations + 1 last-iterate
#define GB 128                // blocks, 1/SM, all wave-1 co-resident (barrier-safe)
#define TB 1024               // threads (32 warps)
#define ROWS_S 28             // rows held in smem per block   (128*28 = 3584)
#define ROWS_L 4              // rows left in L2 per block     (128*4  =  512)
#define ROW0_L (GB * ROWS_S)  // first L2-resident row (3584)
#define CPB 32                // columns owned per block (phase B reduce)
#define SLAB_BYTES (ROWS_S * NN * 2)   // 229376 B dynamic smem

// ---- device-global scratch (static; no cudaMalloc allowed) ----
__device__ __align__(16) __half d_Kh[(size_t)NN * NN];   // K=param^2 fp16 (32MB, L2)
__device__ __align__(16) float  d_Part[(size_t)GB * NN]; // phase-B partials (2MB)
__device__ __align__(16) __half d_BFh[NN];               // BF as fp16 (phase A operand)
__device__ float d_AF[NN];
__device__ float d_BF[NN];
__device__ unsigned int d_bar;  // reset to 0 after each solve by reset_kernel

// ---------------------------------------------------------------------------
// Grid barrier: returnless atomicAdd arrival (RED), static target.
// __threadfence() = gpu scope -> CCTL.IVALL: post-barrier LDGs see fresh data.
// ---------------------------------------------------------------------------
__device__ __forceinline__ void grid_sync(unsigned int target) {
    __syncthreads();
    if (threadIdx.x == 0) {
        __threadfence();                          // release
        atomicAdd(&d_bar, 1u);                    // return unused -> RED
        while (*((volatile unsigned int*)&d_bar) < target) { }
        __threadfence();                          // acquire (L1 invalidate)
    }
    __syncthreads();
}

__global__ void reset_kernel() { d_bar = 0u; }

// ---------------------------------------------------------------------------
// Setup: Kh = float2half(param^2). 8 elems/thread, exact coverage.
// ---------------------------------------------------------------------------
__global__ void setup_kernel(const float* __restrict__ param) {
    size_t base = ((size_t)blockIdx.x * blockDim.x + threadIdx.x) * 8;
    float4 p0 = *(const float4*)(param + base);
    float4 p1 = *(const float4*)(param + base + 4);
    __half2 hs[4];
    hs[0] = __floats2half2_rn(p0.x * p0.x, p0.y * p0.y);
    hs[1] = __floats2half2_rn(p0.z * p0.z, p0.w * p0.w);
    hs[2] = __floats2half2_rn(p1.x * p1.x, p1.y * p1.y);
    hs[3] = __floats2half2_rn(p1.z * p1.z, p1.w * p1.w);
    *reinterpret_cast<uint4*>(d_Kh + base) = *reinterpret_cast<uint4*>(hs);
}

// BF_0 = BT in fp16 (phase A always reads d_BFh).
__global__ void init_bfh_kernel(const float* __restrict__ BT) {
    int i = blockIdx.x * blockDim.x + threadIdx.x;
    d_BFh[i] = __float2half(BT[i]);
}

// ---------------------------------------------------------------------------
// Row dot in packed fp16: 4 HFMA2 per uint4, fp32 flush every 2 uint4s
// (chain <= 4 products per half2 component -> partial <= 4.0, safe in fp16).
// ---------------------------------------------------------------------------
__device__ __forceinline__ float row_dot_h(const uint4* __restrict__ kr,
                                           const uint4* __restrict__ bfh4,
                                           int lane) {
    float fx = 0.f, fy = 0.f;
    #pragma unroll
    for (int grp = 0; grp < 8; ++grp) {
        uint4 k0 = kr[lane + 32 * (2 * grp)];
        uint4 k1 = kr[lane + 32 * (2 * grp + 1)];
        uint4 b0 = bfh4[lane + 32 * (2 * grp)];
        uint4 b1 = bfh4[lane + 32 * (2 * grp + 1)];
        __half2 h0 = __float2half2_rn(0.f);
        __half2 h1 = __float2half2_rn(0.f);
        h0 = __hfma2(*(const __half2*)&k0.x, *(const __half2*)&b0.x, h0);
        h1 = __hfma2(*(const __half2*)&k0.y, *(const __half2*)&b0.y, h1);
        h0 = __hfma2(*(const __half2*)&k0.z, *(const __half2*)&b0.z, h0);
        h1 = __hfma2(*(const __half2*)&k0.w, *(const __half2*)&b0.w, h1);
        h0 = __hfma2(*(const __half2*)&k1.x, *(const __half2*)&b1.x, h0);
        h1 = __hfma2(*(const __half2*)&k1.y, *(const __half2*)&b1.y, h1);
        h0 = __hfma2(*(const __half2*)&k1.z, *(const __half2*)&b1.z, h0);
        h1 = __hfma2(*(const __half2*)&k1.w, *(const __half2*)&b1.w, h1);
        float2 f0 = __half22float2(h0);
        float2 f1 = __half22float2(h1);
        fx += f0.x + f1.x;
        fy += f0.y + f1.y;
    }
    return fx + fy;
}

// ---------------------------------------------------------------------------
// Persistent solver: 128 blocks x 32 warps, smem-resident K slab, HFMA2 math.
//  Block b owns: smem rows [28b,+28), L2 rows [3584+4b,+4), cols [32b,+32).
//  A:  AF[own rows] = AT/(1 + K_row . BFh)         (1 row/warp)
//  Bp: Part[b][c]   = sum_{own rows} AF[i]K[i][c]  (4 cols/thread, no barrier vs A)
//  -- grid_sync --
//  Br: BF[own cols] = BT/(1 + sum_b' Part[b'][c]); also writes d_BFh
//  -- grid_sync --
//  C:  C = param^2 * AF x BF  (exact fp32 param).
// ---------------------------------------------------------------------------
__global__ void __launch_bounds__(TB, 1) solve_kernel(
    const float* __restrict__ AT,
    const float* __restrict__ BT,
    const float* __restrict__ param,
    float* __restrict__ C)
{
    extern __shared__ __align__(16) char smem_raw[];
    __half* slab = (__half*)smem_raw;            // [ROWS_S][NN]
    __shared__ float sAFs[32];                   // this block's AF (28 smem + 4 L2 rows)

    const int tid  = threadIdx.x;
    const int lane = tid & 31;
    const int w    = tid >> 5;                   // warp 0..31
    const int b    = blockIdx.x;
    const int c0   = b * CPB;

    // ---- load this block's 28-row slab from d_Kh (L2-resident) ----
    {
        const uint4* src = (const uint4*)(d_Kh + (size_t)b * ROWS_S * NN);
        uint4*       dst = (uint4*)slab;
        #pragma unroll
        for (int i = 0; i < (ROWS_S * NN / 8) / TB; ++i)   // 14 uint4 per thread
            dst[tid + i * TB] = src[tid + i * TB];
    }
    __syncthreads();

    unsigned int bar_gen = 0;
    const uint4* __restrict__ bfh4 = (const uint4*)d_BFh;

    for (int it = 0; it < ITERS; ++it) {
        // ================= Phase A: row dots, 1 row per warp =================
        float a;
        int row;
        if (w < ROWS_S) {
            row = b * ROWS_S + w;
            a = row_dot_h((const uint4*)(slab + (size_t)w * NN), bfh4, lane);
        } else {
            row = ROW0_L + b * ROWS_L + (w - ROWS_S);
            a = row_dot_h((const uint4*)(d_Kh + (size_t)row * NN), bfh4, lane);
        }
        #pragma unroll
        for (int off = 16; off > 0; off >>= 1)
            a += __shfl_xor_sync(0xffffffffu, a, off);
        if (lane == 0) {
            float af = AT[row] / (1.0f + a);
            sAFs[w]   = af;
            d_AF[row] = af;
        }
        __syncthreads();   // sAFs ready (block-local)

        // ====== Phase Bp: Part[b][c] = sum_{own rows} AF[i]*K[i][c] ======
        // thread owns 4 consecutive columns [4*tid, 4*tid+4)
        {
            float c0f = 0.f, c1f = 0.f, c2f = 0.f, c3f = 0.f;
            #pragma unroll
            for (int grpv = 0; grpv < 8; ++grpv) {           // 8 groups x 4 rows
                __half2 a0 = __float2half2_rn(0.f);
                __half2 a1 = __float2half2_rn(0.f);
                #pragma unroll
                for (int rr = 0; rr < 4; ++rr) {
                    const int r = grpv * 4 + rr;             // 0..31
                    uint2 kv;
                    if (r < ROWS_S)
                        kv = ((const uint2*)(slab + (size_t)r * NN))[tid];
                    else
                        kv = ((const uint2*)(d_Kh +
                              (size_t)(ROW0_L + b * ROWS_L + (r - ROWS_S)) * NN))[tid];
                    __half2 afh = __float2half2_rn(sAFs[r]);
                    a0 = __hfma2(*(const __half2*)&kv.x, afh, a0);
                    a1 = __hfma2(*(const __half2*)&kv.y, afh, a1);
                }
                float2 f0 = __half22float2(a0);
                float2 f1 = __half22float2(a1);
                c0f += f0.x; c1f += f0.y; c2f += f1.x; c3f += f1.y;
            }
            *(float4*)(d_Part + (size_t)b * NN + tid * 4) =
                make_float4(c0f, c1f, c2f, c3f);
        }

        bar_gen += GB;
        grid_sync(bar_gen);

        // ====== Phase Br: BF[own cols] over 128 partials ======
        {
            const int col = c0 + w;                 // 32 cols, one per warp
            float s = 0.f;
            #pragma unroll
            for (int j = 0; j < 4; ++j)             // lane covers partial-blocks lane*4+j
                s += d_Part[(size_t)(lane * 4 + j) * NN + col];
            #pragma unroll
            for (int off = 16; off > 0; off >>= 1)
                s += __shfl_xor_sync(0xffffffffu, s, off);
            if (lane == 0) {
                float bf = BT[col] / (1.0f + s);
                d_BF[col]  = bf;
                d_BFh[col] = __float2half(bf);
            }
        }

        bar_gen += GB;
        grid_sync(bar_gen);
    }

    // ---------------- Phase C: C = param^2 * AF x BF (exact fp32) ----------------
    // 32 warps, 1 row per warp; 32 segs x 32 lanes x float4 = 4096 cols (FULL row).
    const float4* __restrict__ bfv = (const float4*)d_BF;   // fresh post-barrier
    {
        const int   row = b * 32 + w;                        // 32 rows per block
        const float af  = d_AF[row];
        const float4* prow = (const float4*)(param + (size_t)row * NN);
        float4*       crow = (float4*)(C + (size_t)row * NN);
        #pragma unroll 4
        for (int seg = 0; seg < 32; ++seg) {                 // FIX: was seg < 4
            int idx = lane + 32 * seg;
            float4 p = prow[idx];
            float4 f = bfv[idx];
            float4 o;
            o.x = p.x * p.x * af * f.x;
            o.y = p.y * p.y * af * f.y;
            o.z = p.z * p.z * af * f.z;
            o.w = p.w * p.w * af * f.w;
            crow[idx] = o;
        }
    }
}

// ---------------------------------------------------------------------------
extern "C" void kernel_launch(void* const* d_in, const int* in_sizes, int n_in,
                              void* d_out, int out_size) {
    // param is the 16M-element input; AT, BT are the two 4096-element inputs in order.
    int pi = 2;
    for (int i = 0; i < n_in; ++i)
        if (in_sizes[i] == NN * NN) pi = i;
    const float* vecs[2] = {nullptr, nullptr};
    int k = 0;
    for (int i = 0; i < n_in && k < 2; ++i)
        if (i != pi) vecs[k++] = (const float*)d_in[i];
    const float* AT    = vecs[0];
    const float* BT    = vecs[1];
    const float* param = (const float*)d_in[pi];
    float* C = (float*)d_out;

    // Opt into 224 KB dynamic smem (host-side attr; idempotent, not captured).
    static bool attr_done = false;
    if (!attr_done) {
        cudaFuncSetAttribute(solve_kernel,
                             cudaFuncAttributeMaxDynamicSharedMemorySize, SLAB_BYTES);
        attr_done = true;
    }

    // Kh = fp16(param^2): 16,777,216 / (256*8) = 8192 blocks exact.
    setup_kernel<<<8192, 256>>>(param);
    // BF_0 = BT in fp16.
    init_bfh_kernel<<<NN / 256, 256>>>(BT);
    // Persistent solver: 128 blocks, 1/SM, co-resident (barrier-safe).
    solve_kernel<<<GB, TB, SLAB_BYTES>>>(AT, BT, param, C);
    // Restore d_bar = 0 for the next replay (stream-ordered; graph-capturable).
    reset_kernel<<<1, 1>>>();
}

// round 16
// speedup vs baseline: 1.4249x; 1.0439x over previous
#include <cuda_runtime.h>
#include <cuda_fp16.h>

#define NN 4096
#define ITERS 21              // 20 scan iterations + 1 last-iterate
#define GB 148                // blocks, 1/SM on B300(148)/GB300(152) -> co-resident, barrier-safe
#define TB 1024               // threads (32 warps)
#define ROWS_S 27             // smem rows per block (148*27 = 3996)
#define NEXTRA 100            // blocks 0..99 own one extra L2 row (3996..4095)
#define ROW0_X (GB * ROWS_S)  // 3996
#define SLAB_BYTES (ROWS_S * NN * 2)   // 221184 B dynamic smem

// ---- device-global scratch (static; no cudaMalloc allowed) ----
__device__ __align__(16) __half d_Kh[(size_t)NN * NN];    // only rows 3996..4095 used
__device__ __align__(16) float  d_Part[(size_t)152 * NN]; // phase-B partials
__device__ __align__(16) __half d_BFh[NN];                // BF as fp16 (phase A operand)
__device__ float d_AF[NN];
__device__ float d_BF[NN];
__device__ unsigned int d_bar;  // reset to 0 after each solve by reset_kernel

// column/row ownership: blocks 0..99 own 28, blocks 100..147 own 27
__device__ __forceinline__ int owner_base(int b) {
    return (b < NEXTRA) ? 28 * b : 2800 + 27 * (b - NEXTRA);
}
__device__ __forceinline__ int owner_count(int b) {
    return (b < NEXTRA) ? 28 : 27;
}

// ---------------------------------------------------------------------------
// Grid barrier: returnless atomicAdd arrival (RED), static target.
// __threadfence() = gpu scope -> CCTL.IVALL: post-barrier LDGs see fresh data.
// ---------------------------------------------------------------------------
__device__ __forceinline__ void grid_sync(unsigned int target) {
    __syncthreads();
    if (threadIdx.x == 0) {
        __threadfence();                          // release
        atomicAdd(&d_bar, 1u);                    // return unused -> RED
        while (*((volatile unsigned int*)&d_bar) < target) { }
        __threadfence();                          // acquire (L1 invalidate)
    }
    __syncthreads();
}

__global__ void reset_kernel() { d_bar = 0u; }

// ---------------------------------------------------------------------------
// Row dot in packed fp16: per flush-group, 16 HFMA2 (8 products/component,
// |partial| <= 8, safe) then one fp32 flush. 4 groups cover 4096 elements.
// ---------------------------------------------------------------------------
__device__ __forceinline__ float row_dot_h(const uint4* __restrict__ kr,
                                           const uint4* __restrict__ bfh4,
                                           int lane) {
    float fx = 0.f, fy = 0.f;
    #pragma unroll
    for (int grp = 0; grp < 4; ++grp) {
        __half2 h0 = __float2half2_rn(0.f);
        __half2 h1 = __float2half2_rn(0.f);
        #pragma unroll
        for (int s = 0; s < 4; ++s) {
            int g = lane + 32 * (grp * 4 + s);
            uint4 k  = kr[g];
            uint4 bb = bfh4[g];
            h0 = __hfma2(*(const __half2*)&k.x, *(const __half2*)&bb.x, h0);
            h1 = __hfma2(*(const __half2*)&k.y, *(const __half2*)&bb.y, h1);
            h0 = __hfma2(*(const __half2*)&k.z, *(const __half2*)&bb.z, h0);
            h1 = __hfma2(*(const __half2*)&k.w, *(const __half2*)&bb.w, h1);
        }
        float2 f0 = __half22float2(h0);
        float2 f1 = __half22float2(h1);
        fx += f0.x + f1.x;
        fy += f0.y + f1.y;
    }
    return fx + fy;
}

// ---------------------------------------------------------------------------
// Single persistent kernel: builds its own K partition (fp16 of param^2)
// straight into smem, runs 21 Gauss-Seidel iterations with 2 grid barriers
// each, then writes C = param^2 * AF x BF.
// ---------------------------------------------------------------------------
__global__ void __launch_bounds__(TB, 1) solve_kernel(
    const float* __restrict__ AT,
    const float* __restrict__ BT,
    const float* __restrict__ param,
    float* __restrict__ C)
{
    extern __shared__ __align__(16) char smem_raw[];
    __half* slab = (__half*)smem_raw;            // [ROWS_S][NN]
    __shared__ unsigned sAFh[28];                // AF as half2 (broadcast operand for Bp)

    const int tid  = threadIdx.x;
    const int lane = tid & 31;
    const int w    = tid >> 5;                   // warp 0..31
    const int b    = blockIdx.x;
    const bool has_extra = (b < NEXTRA);
    const int rowx = ROW0_X + b;                 // this block's extra row (if any)

    // ====== Build K partition: slab = fp16((param rows)^2), straight from DRAM ======
    {
        const float4* psrc = (const float4*)(param + (size_t)b * ROWS_S * NN);
        uint2* dst = (uint2*)slab;
        #pragma unroll 3
        for (int i = tid; i < ROWS_S * NN / 4; i += TB) {   // 27 iters/thread exact
            float4 p = psrc[i];
            __half2 h0 = __floats2half2_rn(p.x * p.x, p.y * p.y);
            __half2 h1 = __floats2half2_rn(p.z * p.z, p.w * p.w);
            uint2 v;
            v.x = *(unsigned*)&h0;
            v.y = *(unsigned*)&h1;
            dst[i] = v;
        }
    }
    if (has_extra) {                             // extra row -> global d_Kh
        float4 p = ((const float4*)(param + (size_t)rowx * NN))[tid];
        __half2 h0 = __floats2half2_rn(p.x * p.x, p.y * p.y);
        __half2 h1 = __floats2half2_rn(p.z * p.z, p.w * p.w);
        uint2 v;
        v.x = *(unsigned*)&h0;
        v.y = *(unsigned*)&h1;
        ((uint2*)(d_Kh + (size_t)rowx * NN))[tid] = v;
    }
    {   // BF_0 = fp16(BT): every block writes the identical vector (benign race)
        float4 t4 = ((const float4*)BT)[tid];
        __half2 h0 = __floats2half2_rn(t4.x, t4.y);
        __half2 h1 = __floats2half2_rn(t4.z, t4.w);
        uint2 v;
        v.x = *(unsigned*)&h0;
        v.y = *(unsigned*)&h1;
        ((uint2*)d_BFh)[tid] = v;
    }
    __syncthreads();

    unsigned int bar_gen = 0;
    const uint4* __restrict__ bfh4 = (const uint4*)d_BFh;

    for (int it = 0; it < ITERS; ++it) {
        // ================= Phase A: row dots, 1 row per warp =================
        if (w < ROWS_S) {
            const int row = b * ROWS_S + w;
            float a = row_dot_h((const uint4*)(slab + (size_t)w * NN), bfh4, lane);
            #pragma unroll
            for (int off = 16; off > 0; off >>= 1)
                a += __shfl_xor_sync(0xffffffffu, a, off);
            if (lane == 0) {
                float af = AT[row] / (1.0f + a);
                d_AF[row] = af;
                __half2 hh = __float2half2_rn(af);
                sAFh[w] = *(unsigned*)&hh;
            }
        } else if (w == ROWS_S && has_extra) {
            float a = row_dot_h((const uint4*)(d_Kh + (size_t)rowx * NN), bfh4, lane);
            #pragma unroll
            for (int off = 16; off > 0; off >>= 1)
                a += __shfl_xor_sync(0xffffffffu, a, off);
            if (lane == 0) {
                float af = AT[rowx] / (1.0f + a);
                d_AF[rowx] = af;
                __half2 hh = __float2half2_rn(af);
                sAFh[27] = *(unsigned*)&hh;
            }
        }
        __syncthreads();   // sAFh ready (block-local)

        // ====== Phase Bp: Part[b][c] = sum_{own rows} AF[i]*K[i][c] ======
        // thread owns 4 consecutive columns [4*tid, 4*tid+4)
        {
            float c0f = 0.f, c1f = 0.f, c2f = 0.f, c3f = 0.f;
            #pragma unroll
            for (int ch = 0; ch < 3; ++ch) {               // 3 chains x 9 rows = 27
                __half2 a0 = __float2half2_rn(0.f);
                __half2 a1 = __float2half2_rn(0.f);
                #pragma unroll
                for (int rr = 0; rr < 9; ++rr) {
                    const int r = ch * 9 + rr;
                    uint2 kv = ((const uint2*)(slab + (size_t)r * NN))[tid];
                    __half2 afh = *(const __half2*)&sAFh[r];
                    a0 = __hfma2(*(const __half2*)&kv.x, afh, a0);
                    a1 = __hfma2(*(const __half2*)&kv.y, afh, a1);
                }
                float2 f0 = __half22float2(a0);
                float2 f1 = __half22float2(a1);
                c0f += f0.x; c1f += f0.y; c2f += f1.x; c3f += f1.y;
            }
            if (has_extra) {                               // the 28th row
                uint2 kv = ((const uint2*)(d_Kh + (size_t)rowx * NN))[tid];
                __half2 afh = *(const __half2*)&sAFh[27];
                __half2 a0 = __hmul2(*(const __half2*)&kv.x, afh);
                __half2 a1 = __hmul2(*(const __half2*)&kv.y, afh);
                float2 f0 = __half22float2(a0);
                float2 f1 = __half22float2(a1);
                c0f += f0.x; c1f += f0.y; c2f += f1.x; c3f += f1.y;
            }
            *(float4*)(d_Part + (size_t)b * NN + tid * 4) =
                make_float4(c0f, c1f, c2f, c3f);
        }

        bar_gen += GB;
        grid_sync(bar_gen);

        // ====== Phase Br: BF[own cols] over 148 partial rows ======
        {
            const int ncols = owner_count(b);
            if (w < ncols) {
                const int col = owner_base(b) + w;
                float s = 0.f;
                for (int j = lane; j < GB; j += 32)        // fixed ascending order
                    s += d_Part[(size_t)j * NN + col];
                #pragma unroll
                for (int off = 16; off > 0; off >>= 1)
                    s += __shfl_xor_sync(0xffffffffu, s, off);
                if (lane == 0) {
                    float bf = BT[col] / (1.0f + s);
                    d_BF[col]  = bf;
                    d_BFh[col] = __float2half(bf);
                }
            }
        }

        bar_gen += GB;
        grid_sync(bar_gen);
    }

    // ---------------- Phase C: C = param^2 * AF x BF (exact fp32) ----------------
    {
        const int nrows = owner_count(b);
        const int r0    = owner_base(b);
        const float4* __restrict__ bfv = (const float4*)d_BF;   // fresh post-barrier
        if (w < nrows) {
            const int   row = r0 + w;
            const float af  = d_AF[row];
            const float4* prow = (const float4*)(param + (size_t)row * NN);
            float4*       crow = (float4*)(C + (size_t)row * NN);
            #pragma unroll 4
            for (int seg = 0; seg < 32; ++seg) {
                int idx = lane + 32 * seg;
                float4 p = prow[idx];
                float4 f = bfv[idx];
                float4 o;
                o.x = p.x * p.x * af * f.x;
                o.y = p.y * p.y * af * f.y;
                o.z = p.z * p.z * af * f.z;
                o.w = p.w * p.w * af * f.w;
                crow[idx] = o;
            }
        }
    }
}

// ---------------------------------------------------------------------------
extern "C" void kernel_launch(void* const* d_in, const int* in_sizes, int n_in,
                              void* d_out, int out_size) {
    // param is the 16M-element input; AT, BT are the two 4096-element inputs in order.
    int pi = 2;
    for (int i = 0; i < n_in; ++i)
        if (in_sizes[i] == NN * NN) pi = i;
    const float* vecs[2] = {nullptr, nullptr};
    int k = 0;
    for (int i = 0; i < n_in && k < 2; ++i)
        if (i != pi) vecs[k++] = (const float*)d_in[i];
    const float* AT    = vecs[0];
    const float* BT    = vecs[1];
    const float* param = (const float*)d_in[pi];
    float* C = (float*)d_out;

    // Opt into 216 KB dynamic smem (host-side attr; idempotent, not captured).
    static bool attr_done = false;
    if (!attr_done) {
        cudaFuncSetAttribute(solve_kernel,
                             cudaFuncAttributeMaxDynamicSharedMemorySize, SLAB_BYTES);
        attr_done = true;
    }

    // Single persistent solver: 148 blocks, 1/SM, co-resident (barrier-safe).
    solve_kernel<<<GB, TB, SLAB_BYTES>>>(AT, BT, param, C);
    // Restore d_bar = 0 for the next replay (stream-ordered; graph-capturable).
    reset_kernel<<<1, 1>>>();
}